// round 14
// baseline (speedup 1.0000x reference)
#include <cuda_runtime.h>
#include <cuda_fp16.h>

#define T_STEPS 256
#define NN      64
#define HH      512
#define DT_C    0.01f
#define NBLK    128
#define NTHR    1024
#define NWARP   32
#define CHUNK   256
#define RPW     8                                   // j-rows per warp per matrix
#define RES_X   5                                   // resident Wx rows per warp
#define DYN_SMEM (NWARP * RES_X * 64 * 16)          // 32*5*1024 = 163840 B

// fp16 transposed weights: layout [n][j][i]
__device__ __half g_Wh[(size_t)NN * HH * HH];
__device__ __half g_Wx[(size_t)NN * HH * HH];
// partial-sum exchange, parity double-buffered: [par][n][c][i]
__device__ float g_partial[2 * NN * 2 * HH];
__device__ unsigned g_chunk_cnt[2 * 32];   // per-chunk hy counters (128B apart)
__device__ unsigned g_part_cnt[NN];        // +2 per neuron per step

// ---------------------------------------------------------------------------
__device__ __forceinline__ void arrive_rel(unsigned* ctr)
{
    asm volatile("red.release.gpu.add.u32 [%0], 1;" :: "l"(ctr) : "memory");
}
__device__ __forceinline__ unsigned ld_acq(unsigned* ctr)
{
    unsigned v;
    asm volatile("ld.acquire.gpu.u32 %0, [%1];" : "=r"(v) : "l"(ctr) : "memory");
    return v;
}
__device__ __forceinline__ void spin_until(unsigned* ctr, unsigned target)
{
    if (ld_acq(ctr) >= target) return;
    while (ld_acq(ctr) < target) __nanosleep(20);
}

// ---------------------------------------------------------------------------
// fp32 [n][i][j]  ->  fp16 [n][j][i]   (transpose + convert, tiled)
// ---------------------------------------------------------------------------
__global__ void convert_transpose_kernel(const float* __restrict__ src, int which)
{
    __shared__ float tile[32][33];
    __half* dst = which ? g_Wx : g_Wh;
    const int nmat = blockIdx.z;
    const float* s = src + (size_t)nmat * HH * HH;
    __half*      d = dst + (size_t)nmat * HH * HH;
    const int x0 = blockIdx.x * 32;
    const int y0 = blockIdx.y * 32;
    #pragma unroll
    for (int k = threadIdx.y; k < 32; k += 8)
        tile[k][threadIdx.x] = s[(size_t)(y0 + k) * HH + x0 + threadIdx.x];
    __syncthreads();
    #pragma unroll
    for (int k = threadIdx.y; k < 32; k += 8)
        d[(size_t)(x0 + k) * HH + y0 + threadIdx.x] = __float2half_rn(tile[threadIdx.x][k]);
}

// ---------------------------------------------------------------------------
__global__ void init_out_kernel(const float* __restrict__ x,
                                const float* __restrict__ init_states,
                                float* __restrict__ states,
                                float* __restrict__ ins)
{
    const int i = blockIdx.x * blockDim.x + threadIdx.x;
    if (i < NN * 2 * HH) states[i] = init_states[i];
    if (i < NN * HH)     ins[i]    = x[i];
    if (i < NN)          g_part_cnt[i] = 0;
    if (i < 2 * 32)      g_chunk_cnt[i] = 0;
}

// ---------------------------------------------------------------------------
__device__ __forceinline__ void fma8(float* acc, uint4 a, float v)
{
    float2 f;
    f = __half22float2(*reinterpret_cast<__half2*>(&a.x)); acc[0] += f.x * v; acc[1] += f.y * v;
    f = __half22float2(*reinterpret_cast<__half2*>(&a.y)); acc[2] += f.x * v; acc[3] += f.y * v;
    f = __half22float2(*reinterpret_cast<__half2*>(&a.z)); acc[4] += f.x * v; acc[5] += f.y * v;
    f = __half22float2(*reinterpret_cast<__half2*>(&a.w)); acc[6] += f.x * v; acc[7] += f.y * v;
}

// ---------------------------------------------------------------------------
// persistent RNN, j-partitioned, perfectly balanced: 128 blocks x 1024 thr,
// 1 block/SM, 2 blocks per neuron.  Block (n,c) owns j-chunk = i-chunk c
// (256 indices); warp w owns 8 rows of each matrix (same loop as R12).
//  - Wh partial: local hy chunk only -> covers the chunk wait.
//  - ins chunk computed locally -> no ins exchange.
//  - single exchange per step: 512-float partials, ONE sibling.
// ---------------------------------------------------------------------------
__global__ void __launch_bounds__(NTHR, 1) rnn_kernel(
    const float* __restrict__ x,      // [T][N][H]
    const float* __restrict__ C,      // [N][N]
    const float* __restrict__ b,      // [N][H]
    float* __restrict__ states,       // [T+1][N][2][H]
    float* __restrict__ ins)          // [T+1][N][H]
{
    extern __shared__ __align__(16) unsigned char dynsmem[];
    uint4* sres = reinterpret_cast<uint4*>(dynsmem);

    __shared__ __align__(16) float sh_red[16 * HH];  // 32 KB reduce buffer
    __shared__ float sh_hy[CHUNK];
    __shared__ float sh_ins[CHUNK];
    __shared__ float sh_C[NN];
    __shared__ float sh_cm[4 * CHUNK];

    const int bid  = blockIdx.x;
    const int n    = bid >> 1;
    const int c    = bid & 1;
    const int cb   = c * CHUNK;
    const int tid  = threadIdx.x;
    const int w    = tid >> 5;
    const int lane = tid & 31;

    if (tid < NN) sh_C[tid] = C[n * NN + tid];
    const float bias = (tid < CHUNK) ? b[n * HH + cb + tid] : 0.0f;
    float hz_r = (tid < CHUNK) ? states[(n * 2 + 1) * HH + cb + tid] : 0.0f;
    if (tid < CHUNK) sh_hy[tid] = states[(n * 2 + 0) * HH + cb + tid];
    float xv = (tid < CHUNK) ? x[(size_t)n * HH + cb + tid] : 0.0f;

    // warp w owns j-rows cb + w*8 .. +7 of both matrices
    const __half* pWh = g_Wh + (size_t)n * HH * HH + (size_t)(cb + w * RPW) * HH;
    const __half* pWx = g_Wx + (size_t)n * HH * HH + (size_t)(cb + w * RPW) * HH;

    // stage resident Wx rows 0..RES_X-1 (per warp)
    for (int r = 0; r < RES_X; ++r) {
        const uint4* rp = reinterpret_cast<const uint4*>(pWx + (size_t)r * HH);
        sres[(w * RES_X + r) * 64 + lane]      = rp[lane];
        sres[(w * RES_X + r) * 64 + 32 + lane] = rp[lane + 32];
    }
    __syncthreads();

    for (int t = 0; t < T_STEPS; ++t) {
        const float* st  = states + (size_t)t * NN * 2 * HH;
        float*       stn = states + (size_t)(t + 1) * NN * 2 * HH;
        const int par = t & 1;

        float acc[16];
        #pragma unroll
        for (int k = 0; k < 16; ++k) acc[k] = 0.0f;

        // ---- Wh partial: local hy chunk, streamed from L2 (covers wait) ----
        #pragma unroll 4
        for (int r = 0; r < RPW; ++r) {
            const float v = sh_hy[w * RPW + r];
            const uint4* rp = reinterpret_cast<const uint4*>(pWh + (size_t)r * HH);
            fma8(acc,     rp[lane],      v);
            fma8(acc + 8, rp[lane + 32], v);
        }

        // ---- chunk wait: all 64 blocks of chunk group c stored hy(t) -------
        if (t > 0) {
            if (tid == 0) spin_until(&g_chunk_cnt[c * 32], 64u * (unsigned)t);
            __syncthreads();                                        // bar A
        }

        // ---- C-mix for own 256 j's (4-way m-split over 1024 threads) -------
        {
            const int jloc = tid & 255;
            const int mg   = tid >> 8;           // 0..3
            float cm = 0.0f;
            if (t > 0) {
                const float* sp = st + (size_t)(2 * mg * 16) * HH + cb + jloc;
                #pragma unroll 8
                for (int m = 0; m < 16; ++m)
                    cm += sh_C[mg * 16 + m] * sp[(size_t)m * 2 * HH];
            }
            sh_cm[mg * CHUNK + jloc] = cm;
        }
        __syncthreads();                                            // bar B
        if (tid < CHUNK) {
            const float v = (t > 0)
                ? (sh_cm[tid] + sh_cm[CHUNK + tid] + sh_cm[2 * CHUNK + tid] + sh_cm[3 * CHUNK + tid]) * xv
                : 0.0f;
            sh_ins[tid] = v;
            ins[((size_t)(t + 1) * NN + n) * HH + cb + tid] = v;    // output only
        }
        __syncthreads();                                            // bar C

        // ---- Wx partial: streamed tail first, then resident ----------------
        #pragma unroll
        for (int r = RES_X; r < RPW; ++r) {
            const float v = sh_ins[w * RPW + r];
            const uint4* rp = reinterpret_cast<const uint4*>(pWx + (size_t)r * HH);
            fma8(acc,     rp[lane],      v);
            fma8(acc + 8, rp[lane + 32], v);
        }
        #pragma unroll
        for (int r = 0; r < RES_X; ++r) {
            const float v = sh_ins[w * RPW + r];
            fma8(acc,     sres[(w * RES_X + r) * 64 + lane],      v);
            fma8(acc + 8, sres[(w * RES_X + r) * 64 + 32 + lane], v);
        }

        // ---- in-block reduce: 32 warps -> 16 -> final sum-of-16 ------------
        if (w >= 16) {
            float* pp = sh_red + (w - 16) * HH;
            *reinterpret_cast<float4*>(pp + lane * 8)           = make_float4(acc[0], acc[1], acc[2], acc[3]);
            *reinterpret_cast<float4*>(pp + lane * 8 + 4)       = make_float4(acc[4], acc[5], acc[6], acc[7]);
            *reinterpret_cast<float4*>(pp + 256 + lane * 8)     = make_float4(acc[8], acc[9], acc[10], acc[11]);
            *reinterpret_cast<float4*>(pp + 256 + lane * 8 + 4) = make_float4(acc[12], acc[13], acc[14], acc[15]);
        }
        __syncthreads();                                            // bar D
        if (w < 16) {
            float* pp = sh_red + w * HH;
            float4 q0 = *reinterpret_cast<float4*>(pp + lane * 8);
            float4 q1 = *reinterpret_cast<float4*>(pp + lane * 8 + 4);
            float4 q2 = *reinterpret_cast<float4*>(pp + 256 + lane * 8);
            float4 q3 = *reinterpret_cast<float4*>(pp + 256 + lane * 8 + 4);
            q0.x += acc[0];  q0.y += acc[1];  q0.z += acc[2];  q0.w += acc[3];
            q1.x += acc[4];  q1.y += acc[5];  q1.z += acc[6];  q1.w += acc[7];
            q2.x += acc[8];  q2.y += acc[9];  q2.z += acc[10]; q2.w += acc[11];
            q3.x += acc[12]; q3.y += acc[13]; q3.z += acc[14]; q3.w += acc[15];
            *reinterpret_cast<float4*>(pp + lane * 8)           = q0;
            *reinterpret_cast<float4*>(pp + lane * 8 + 4)       = q1;
            *reinterpret_cast<float4*>(pp + 256 + lane * 8)     = q2;
            *reinterpret_cast<float4*>(pp + 256 + lane * 8 + 4) = q3;
        }
        __syncthreads();                                            // bar E
        if (tid < HH) {
            float s = 0.0f;
            #pragma unroll
            for (int k = 0; k < 16; ++k) s += sh_red[k * HH + tid];
            g_partial[((size_t)(par * NN + n) * 2 + c) * HH + tid] = s;
        }
        __syncthreads();                                            // bar F
        if (tid == 0) {
            arrive_rel(&g_part_cnt[n]);
            spin_until(&g_part_cnt[n], 2u * (unsigned)(t + 1));
        }
        __syncthreads();                                            // bar G

        // ---- combine 2 partials (fixed order), update own i-chunk ----------
        if (tid < CHUNK) {
            const float* gp = g_partial + (size_t)(par * NN + n) * 2 * HH;
            const float s = bias + gp[cb + tid] + gp[HH + cb + tid];
            const float hy   = sh_hy[tid];
            const float hz_n = hz_r + DT_C * (tanhf(s) - hy - hz_r);   // GAMMA=EPS=1
            const float hy_n = hy + DT_C * hz_n;
            hz_r = hz_n;
            stn[(n * 2 + 0) * HH + cb + tid] = hy_n;
            stn[(n * 2 + 1) * HH + cb + tid] = hz_n;
            sh_hy[tid] = hy_n;
            if (t + 1 < T_STEPS)
                xv = x[((size_t)(t + 1) * NN + n) * HH + cb + tid];
        }
        __syncthreads();                                            // bar H
        if (tid == 0) arrive_rel(&g_chunk_cnt[c * 32]);
    }
}

// ---------------------------------------------------------------------------
extern "C" void kernel_launch(void* const* d_in, const int* in_sizes, int n_in,
                              void* d_out, int out_size)
{
    const float* x   = (const float*)d_in[0];   // (256, 64, 512)
    const float* C   = (const float*)d_in[1];   // (64, 64)
    const float* Wh  = (const float*)d_in[2];   // (64, 512, 512)
    const float* Wx  = (const float*)d_in[3];   // (64, 512, 512)
    const float* b   = (const float*)d_in[4];   // (64, 512)
    const float* s0  = (const float*)d_in[5];   // (64, 2, 512)

    float* out    = (float*)d_out;
    float* states = out;                                          // (257,64,2,512)
    float* ins    = out + (size_t)(T_STEPS + 1) * NN * 2 * HH;    // (257,64,512)

    cudaFuncSetAttribute(rnn_kernel, cudaFuncAttributeMaxDynamicSharedMemorySize, DYN_SMEM);

    dim3 tb(32, 8, 1), tg(16, 16, NN);
    convert_transpose_kernel<<<tg, tb>>>(Wh, 0);
    convert_transpose_kernel<<<tg, tb>>>(Wx, 1);
    init_out_kernel<<<(NN * 2 * HH + 255) / 256, 256>>>(x, s0, states, ins);
    rnn_kernel<<<NBLK, NTHR, DYN_SMEM>>>(x, C, b, states, ins);
}

// round 15
// speedup vs baseline: 1.1703x; 1.1703x over previous
#include <cuda_runtime.h>
#include <cuda_fp16.h>

#define T_STEPS 256
#define NN      64
#define HH      512
#define DT_C    0.01f
#define NBLK    256
#define NTHR    512
#define NWARP   16
#define RPW     16                                  // j-rows per warp (256-i wide)
#define RES_X   10                                  // resident Wx rows per warp
#define DYN_SMEM (NWARP * RES_X * 32 * 16)          // 16*10*512 = 81920 B

// fp16 transposed weights: layout [n][j][i]
__device__ __half g_Wh[(size_t)NN * HH * HH];
__device__ __half g_Wx[(size_t)NN * HH * HH];
// partial-sum exchange, parity double-buffered: [par][n][c][i]
__device__ float g_partial[2 * NN * 4 * HH];
__device__ unsigned g_chunk_cnt[4 * 32];   // per-chunk hy counters (128B apart)
__device__ unsigned g_part_cnt[NN];        // +4 per neuron per step

// ---------------------------------------------------------------------------
__device__ __forceinline__ void arrive_rel(unsigned* ctr)
{
    asm volatile("red.release.gpu.add.u32 [%0], 1;" :: "l"(ctr) : "memory");
}
__device__ __forceinline__ unsigned ld_acq(unsigned* ctr)
{
    unsigned v;
    asm volatile("ld.acquire.gpu.u32 %0, [%1];" : "=r"(v) : "l"(ctr) : "memory");
    return v;
}
__device__ __forceinline__ void spin_until(unsigned* ctr, unsigned target)
{
    if (ld_acq(ctr) >= target) return;
    while (ld_acq(ctr) < target) __nanosleep(20);
}

// ---------------------------------------------------------------------------
// fp32 [n][i][j]  ->  fp16 [n][j][i]   (transpose + convert, tiled)
// ---------------------------------------------------------------------------
__global__ void convert_transpose_kernel(const float* __restrict__ src, int which)
{
    __shared__ float tile[32][33];
    __half* dst = which ? g_Wx : g_Wh;
    const int nmat = blockIdx.z;
    const float* s = src + (size_t)nmat * HH * HH;
    __half*      d = dst + (size_t)nmat * HH * HH;
    const int x0 = blockIdx.x * 32;
    const int y0 = blockIdx.y * 32;
    #pragma unroll
    for (int k = threadIdx.y; k < 32; k += 8)
        tile[k][threadIdx.x] = s[(size_t)(y0 + k) * HH + x0 + threadIdx.x];
    __syncthreads();
    #pragma unroll
    for (int k = threadIdx.y; k < 32; k += 8)
        d[(size_t)(x0 + k) * HH + y0 + threadIdx.x] = __float2half_rn(tile[threadIdx.x][k]);
}

// ---------------------------------------------------------------------------
__global__ void init_out_kernel(const float* __restrict__ x,
                                const float* __restrict__ init_states,
                                float* __restrict__ states,
                                float* __restrict__ ins)
{
    const int i = blockIdx.x * blockDim.x + threadIdx.x;
    if (i < NN * 2 * HH) states[i] = init_states[i];
    if (i < NN * HH)     ins[i]    = x[i];
    if (i < NN)          g_part_cnt[i] = 0;
    if (i < 4 * 32)      g_chunk_cnt[i] = 0;
}

// ---------------------------------------------------------------------------
__device__ __forceinline__ void fma8(float* acc, uint4 a, float v)
{
    float2 f;
    f = __half22float2(*reinterpret_cast<__half2*>(&a.x)); acc[0] += f.x * v; acc[1] += f.y * v;
    f = __half22float2(*reinterpret_cast<__half2*>(&a.y)); acc[2] += f.x * v; acc[3] += f.y * v;
    f = __half22float2(*reinterpret_cast<__half2*>(&a.z)); acc[4] += f.x * v; acc[5] += f.y * v;
    f = __half22float2(*reinterpret_cast<__half2*>(&a.w)); acc[6] += f.x * v; acc[7] += f.y * v;
}

// ---------------------------------------------------------------------------
// persistent RNN, fully j-partitioned (R12 topology): 256 blocks = 4 per
// neuron, 2 blocks/SM, 512 threads.  Block (n,c) owns j-chunk c (128 rows of
// Wh AND Wx) and i-chunk c.  R15: 2-D warp split — warp w = (ig = w>>3,
// jg = w&7) covers 16 j-rows x 256 i-outputs (acc[8]); reduce is a single
// round over 8 partials per output (16 KB sh_red, one barrier).
// ---------------------------------------------------------------------------
__global__ void __launch_bounds__(NTHR, 2) rnn_kernel(
    const float* __restrict__ x,      // [T][N][H]
    const float* __restrict__ C,      // [N][N]
    const float* __restrict__ b,      // [N][H]
    float* __restrict__ states,       // [T+1][N][2][H]
    float* __restrict__ ins)          // [T+1][N][H]
{
    extern __shared__ __align__(16) unsigned char dynsmem[];
    uint4* sres = reinterpret_cast<uint4*>(dynsmem);

    __shared__ __align__(16) float sh_red[NWARP * 256];  // 16 KB reduce buffer
    __shared__ float sh_hy[128];
    __shared__ float sh_ins[128];
    __shared__ float sh_C[NN];
    __shared__ float sh_cm[4 * 128];

    const int bid  = blockIdx.x;
    const int n    = bid >> 2;
    const int c    = bid & 3;
    const int cb   = c * 128;
    const int tid  = threadIdx.x;
    const int w    = tid >> 5;
    const int lane = tid & 31;
    const int ig   = w >> 3;          // i-half: 0 or 1 (256 outputs)
    const int jg   = w & 7;           // j-group: 16 rows

    if (tid < NN) sh_C[tid] = C[n * NN + tid];
    const float bias = (tid < 128) ? b[n * HH + cb + tid] : 0.0f;
    float hz_r = (tid < 128) ? states[(n * 2 + 1) * HH + cb + tid] : 0.0f;
    if (tid < 128) sh_hy[tid] = states[(n * 2 + 0) * HH + cb + tid];
    float xv = (tid < 128) ? x[(size_t)n * HH + cb + tid] : 0.0f;

    // warp (ig,jg): j-rows cb + jg*16 .. +15, i-range ig*256 + lane*8
    const __half* pWh = g_Wh + (size_t)n * HH * HH + (size_t)(cb + jg * RPW) * HH + ig * 256 + lane * 8;
    const __half* pWx = g_Wx + (size_t)n * HH * HH + (size_t)(cb + jg * RPW) * HH + ig * 256 + lane * 8;

    // stage resident Wx rows 0..RES_X-1 (per warp): 1 uint4 per lane per row
    for (int r = 0; r < RES_X; ++r)
        sres[(w * RES_X + r) * 32 + lane] = *reinterpret_cast<const uint4*>(pWx + (size_t)r * HH);
    __syncthreads();

    for (int t = 0; t < T_STEPS; ++t) {
        const float* st  = states + (size_t)t * NN * 2 * HH;
        float*       stn = states + (size_t)(t + 1) * NN * 2 * HH;
        const int par = t & 1;

        float acc[8];
        #pragma unroll
        for (int k = 0; k < 8; ++k) acc[k] = 0.0f;

        // ---- Wh partial: local hy chunk, streamed from L2 (covers wait) ----
        #pragma unroll 4
        for (int r = 0; r < RPW; ++r) {
            const float v = sh_hy[jg * RPW + r];
            fma8(acc, *reinterpret_cast<const uint4*>(pWh + (size_t)r * HH), v);
        }

        // ---- chunk wait: all 64 blocks of chunk group c stored hy(t) -------
        if (t > 0) {
            if (tid == 0) spin_until(&g_chunk_cnt[c * 32], 64u * (unsigned)t);
            __syncthreads();                                        // bar A
        }

        // ---- C-mix for own 128 j's (4-way m-split over 512 threads) --------
        {
            const int jloc = tid & 127;
            const int mg   = tid >> 7;
            float cm = 0.0f;
            if (t > 0) {
                const float* sp = st + (size_t)(2 * mg * 16) * HH + cb + jloc;
                #pragma unroll 8
                for (int m = 0; m < 16; ++m)
                    cm += sh_C[mg * 16 + m] * sp[(size_t)m * 2 * HH];
            }
            sh_cm[mg * 128 + jloc] = cm;
        }
        __syncthreads();                                            // bar B
        if (tid < 128) {
            const float v = (t > 0)
                ? (sh_cm[tid] + sh_cm[128 + tid] + sh_cm[256 + tid] + sh_cm[384 + tid]) * xv
                : 0.0f;
            sh_ins[tid] = v;
            ins[((size_t)(t + 1) * NN + n) * HH + cb + tid] = v;    // output only
        }
        __syncthreads();                                            // bar C

        // ---- Wx partial: streamed tail first (LDG MLP), then resident ------
        #pragma unroll
        for (int r = RES_X; r < RPW; ++r) {
            const float v = sh_ins[jg * RPW + r];
            fma8(acc, *reinterpret_cast<const uint4*>(pWx + (size_t)r * HH), v);
        }
        #pragma unroll
        for (int r = 0; r < RES_X; ++r) {
            const float v = sh_ins[jg * RPW + r];
            fma8(acc, sres[(w * RES_X + r) * 32 + lane], v);
        }

        // ---- single-round reduce: warp w writes 256 partials, sum 8 --------
        {
            float* pp = sh_red + w * 256 + lane * 8;
            *reinterpret_cast<float4*>(pp)     = make_float4(acc[0], acc[1], acc[2], acc[3]);
            *reinterpret_cast<float4*>(pp + 4) = make_float4(acc[4], acc[5], acc[6], acc[7]);
        }
        __syncthreads();                                            // bar D
        {
            const int oi = tid >> 8;          // output i-half
            const int ii = tid & 255;
            float s = 0.0f;
            #pragma unroll
            for (int k = 0; k < 8; ++k) s += sh_red[(oi * 8 + k) * 256 + ii];
            g_partial[((size_t)(par * NN + n) * 4 + c) * HH + tid] = s;
        }
        __syncthreads();                                            // bar F
        if (tid == 0) {
            arrive_rel(&g_part_cnt[n]);
            spin_until(&g_part_cnt[n], 4u * (unsigned)(t + 1));
        }
        __syncthreads();                                            // bar G

        // ---- combine 4 partials (fixed order), update own i-chunk ----------
        if (tid < 128) {
            const float* gp = g_partial + (size_t)(par * NN + n) * 4 * HH;
            float s = bias;
            #pragma unroll
            for (int cc = 0; cc < 4; ++cc) s += gp[cc * HH + cb + tid];
            const float hy   = sh_hy[tid];
            const float hz_n = hz_r + DT_C * (tanhf(s) - hy - hz_r);   // GAMMA=EPS=1
            const float hy_n = hy + DT_C * hz_n;
            hz_r = hz_n;
            stn[(n * 2 + 0) * HH + cb + tid] = hy_n;
            stn[(n * 2 + 1) * HH + cb + tid] = hz_n;
            sh_hy[tid] = hy_n;
            if (t + 1 < T_STEPS)
                xv = x[((size_t)(t + 1) * NN + n) * HH + cb + tid];
        }
        __syncthreads();                                            // bar H
        if (tid == 0) arrive_rel(&g_chunk_cnt[c * 32]);
    }
}

// ---------------------------------------------------------------------------
extern "C" void kernel_launch(void* const* d_in, const int* in_sizes, int n_in,
                              void* d_out, int out_size)
{
    const float* x   = (const float*)d_in[0];   // (256, 64, 512)
    const float* C   = (const float*)d_in[1];   // (64, 64)
    const float* Wh  = (const float*)d_in[2];   // (64, 512, 512)
    const float* Wx  = (const float*)d_in[3];   // (64, 512, 512)
    const float* b   = (const float*)d_in[4];   // (64, 512)
    const float* s0  = (const float*)d_in[5];   // (64, 2, 512)

    float* out    = (float*)d_out;
    float* states = out;                                          // (257,64,2,512)
    float* ins    = out + (size_t)(T_STEPS + 1) * NN * 2 * HH;    // (257,64,512)

    cudaFuncSetAttribute(rnn_kernel, cudaFuncAttributeMaxDynamicSharedMemorySize, DYN_SMEM);

    dim3 tb(32, 8, 1), tg(16, 16, NN);
    convert_transpose_kernel<<<tg, tb>>>(Wh, 0);
    convert_transpose_kernel<<<tg, tb>>>(Wx, 1);
    init_out_kernel<<<(NN * 2 * HH + 255) / 256, 256>>>(x, s0, states, ins);
    rnn_kernel<<<NBLK, NTHR, DYN_SMEM>>>(x, C, b, states, ins);
}